// round 1
// baseline (speedup 1.0000x reference)
#include <cuda_runtime.h>
#include <cuda_bf16.h>
#include <cstdint>

// ---------------------------------------------------------------------------
// GraphConvolution: out = SpMM(COO adj, x @ W) + bias
//   x:        [N_NODES, 512] fp32
//   adj_rows: [E] int32   (destination / segment id)
//   adj_cols: [E] int32   (source node, gathered from support)
//   adj_vals: [E] fp32
//   weight:   [512, 512] fp32
//   bias:     [512] fp32
//   out:      [N_NODES, 512] fp32
// ---------------------------------------------------------------------------

#define D 512           // D_IN == D_OUT == 512
#define MAX_NODES 50000

// Scratch for support = x @ W  (102.4 MB, static device global: allocation-free)
__device__ float g_support[(size_t)MAX_NODES * D];

// ---------------------------------------------------------------------------
// Kernel 1: out[i, :] = bias[:]   (also covers nodes with zero in-edges)
// ---------------------------------------------------------------------------
__global__ void init_out_kernel(float* __restrict__ out,
                                const float* __restrict__ bias,
                                int total_f4) {
    int idx = blockIdx.x * blockDim.x + threadIdx.x;
    if (idx >= total_f4) return;
    // each float4 covers 4 consecutive dims; bias index = (idx % 128) * 4
    const float4 b = reinterpret_cast<const float4*>(bias)[idx & (D / 4 - 1)];
    reinterpret_cast<float4*>(out)[idx] = b;
}

// ---------------------------------------------------------------------------
// Kernel 2: classic register-blocked SGEMM  C[M,N] = A[M,K] * B[K,N]
// BM=128, BN=128, BK=8, 256 threads, 8x8 per-thread microtile.
// N=512, K=512 are multiples of tile dims; only M needs guarding.
// ---------------------------------------------------------------------------
#define BM 128
#define BN 128
#define BK 8
#define TM 8
#define TN 8

__global__ __launch_bounds__(256, 2)
void sgemm_kernel(const float* __restrict__ A,   // [M, K]
                  const float* __restrict__ B,   // [K, N]
                  float* __restrict__ C,         // [M, N]
                  int M, int N, int K) {
    __shared__ float As[BK][BM];   // transposed A tile
    __shared__ float Bs[BK][BN];

    const int bx = blockIdx.x;     // along N
    const int by = blockIdx.y;     // along M
    const int tid = threadIdx.x;

    const int tx = tid % (BN / TN);   // 0..15
    const int ty = tid / (BN / TN);   // 0..15

    // A tile loader: 128 rows x 8 cols = 256 float4 (2 per row)
    const int a_row = tid >> 1;           // 0..127
    const int a_col = (tid & 1) * 4;      // 0 or 4
    // B tile loader: 8 rows x 128 cols = 256 float4 (32 per row)
    const int b_row = tid >> 5;           // 0..7
    const int b_col = (tid & 31) * 4;

    const int m_base = by * BM;
    const float* Ab = A + (size_t)m_base * K;
    const float* Bb = B + bx * BN;

    float acc[TM][TN];
    #pragma unroll
    for (int i = 0; i < TM; i++)
        #pragma unroll
        for (int j = 0; j < TN; j++) acc[i][j] = 0.0f;

    for (int k0 = 0; k0 < K; k0 += BK) {
        // load A tile (guard M), store transposed
        float4 av = make_float4(0.f, 0.f, 0.f, 0.f);
        if (m_base + a_row < M)
            av = *reinterpret_cast<const float4*>(Ab + (size_t)a_row * K + k0 + a_col);
        As[a_col + 0][a_row] = av.x;
        As[a_col + 1][a_row] = av.y;
        As[a_col + 2][a_row] = av.z;
        As[a_col + 3][a_row] = av.w;

        // load B tile
        float4 bv = *reinterpret_cast<const float4*>(Bb + (size_t)(k0 + b_row) * N + b_col);
        *reinterpret_cast<float4*>(&Bs[b_row][b_col]) = bv;

        __syncthreads();

        #pragma unroll
        for (int k = 0; k < BK; k++) {
            float ar[TM], br[TN];
            #pragma unroll
            for (int i = 0; i < TM; i++) ar[i] = As[k][ty * TM + i];
            #pragma unroll
            for (int j = 0; j < TN; j++) br[j] = Bs[k][tx * TN + j];
            #pragma unroll
            for (int i = 0; i < TM; i++)
                #pragma unroll
                for (int j = 0; j < TN; j++)
                    acc[i][j] = fmaf(ar[i], br[j], acc[i][j]);
        }
        __syncthreads();
    }

    // write back (columns are contiguous per thread: two float4 per row)
    const int c_col = bx * BN + tx * TN;
    #pragma unroll
    for (int i = 0; i < TM; i++) {
        int row = m_base + ty * TM + i;
        if (row >= M) break;
        float4* cp = reinterpret_cast<float4*>(C + (size_t)row * N + c_col);
        cp[0] = make_float4(acc[i][0], acc[i][1], acc[i][2], acc[i][3]);
        cp[1] = make_float4(acc[i][4], acc[i][5], acc[i][6], acc[i][7]);
    }
}

// ---------------------------------------------------------------------------
// Kernel 3: COO scatter. One warp per edge; each lane handles 4 float4 (16 f).
// out[row, :] += val * support[col, :]   via red.global.add.v4.f32 (sm_90+).
// ---------------------------------------------------------------------------
__global__ __launch_bounds__(256)
void scatter_kernel(const int* __restrict__ rows,
                    const int* __restrict__ cols,
                    const float* __restrict__ vals,
                    float* __restrict__ out,
                    int E) {
    const int warp = (blockIdx.x * blockDim.x + threadIdx.x) >> 5;
    const int lane = threadIdx.x & 31;
    if (warp >= E) return;

    const int r = rows[warp];
    const int c = cols[warp];
    const float v = vals[warp];

    const float4* s = reinterpret_cast<const float4*>(g_support + (size_t)c * D);
    float4* o = reinterpret_cast<float4*>(out + (size_t)r * D);

    #pragma unroll
    for (int w = 0; w < 4; w++) {
        const int idx = lane + w * 32;       // 0..127 float4 slots
        float4 m = s[idx];
        m.x *= v; m.y *= v; m.z *= v; m.w *= v;
        asm volatile(
            "red.global.add.v4.f32 [%0], {%1, %2, %3, %4};"
            :: "l"(o + idx), "f"(m.x), "f"(m.y), "f"(m.z), "f"(m.w)
            : "memory");
    }
}

// ---------------------------------------------------------------------------
// Launch
// ---------------------------------------------------------------------------
extern "C" void kernel_launch(void* const* d_in, const int* in_sizes, int n_in,
                              void* d_out, int out_size) {
    const float* x        = (const float*)d_in[0];
    const int*   adj_rows = (const int*)  d_in[1];
    const int*   adj_cols = (const int*)  d_in[2];
    const float* adj_vals = (const float*)d_in[3];
    const float* weight   = (const float*)d_in[4];
    const float* bias     = (const float*)d_in[5];
    float* out = (float*)d_out;

    const int M = in_sizes[0] / D;   // N_NODES
    const int E = in_sizes[1];       // N_EDGES

    // 1) out = broadcast(bias)
    {
        int total_f4 = (M * D) / 4;
        int threads = 256;
        int blocks = (total_f4 + threads - 1) / threads;
        init_out_kernel<<<blocks, threads>>>(out, bias, total_f4);
    }

    // 2) support = x @ W  (into static device scratch)
    {
        float* support;
        cudaGetSymbolAddress((void**)&support, g_support);
        dim3 grid(D / BN, (M + BM - 1) / BM);
        sgemm_kernel<<<grid, 256>>>(x, weight, support, M, D, D);
    }

    // 3) out += scatter-add over edges
    {
        int warps_per_block = 256 / 32;
        int blocks = (E + warps_per_block - 1) / warps_per_block;
        scatter_kernel<<<blocks, 256>>>(adj_rows, adj_cols, adj_vals, out, E);
    }
}

// round 2
// speedup vs baseline: 1.7631x; 1.7631x over previous
#include <cuda_runtime.h>
#include <cuda_bf16.h>
#include <cstdint>

// ---------------------------------------------------------------------------
// GraphConvolution: out = SpMM(COO adj, x @ W) + bias
//   x [N,512] fp32, adj (rows, cols, vals) COO [E], W [512,512], bias [512]
//   out [N,512] fp32
// Round 1: GEMM moved to tf32 tensor cores (mma.sync.m16n8k8).
// ---------------------------------------------------------------------------

#define D 512
#define MAX_NODES 50000

__device__ float g_support[(size_t)MAX_NODES * D];

// ---------------------------------------------------------------------------
// Kernel 1: out[i, :] = bias[:]
// ---------------------------------------------------------------------------
__global__ void init_out_kernel(float* __restrict__ out,
                                const float* __restrict__ bias,
                                int total_f4) {
    int idx = blockIdx.x * blockDim.x + threadIdx.x;
    if (idx >= total_f4) return;
    const float4 b = reinterpret_cast<const float4*>(bias)[idx & (D / 4 - 1)];
    reinterpret_cast<float4*>(out)[idx] = b;
}

// ---------------------------------------------------------------------------
// Kernel 2: TF32 tensor-core GEMM  C[M,512] = A[M,512] * B[512,512]
// CTA tile 128x128x16, 8 warps (4x2), warp tile 32x64, mma.m16n8k8.tf32.
// Smem strides padded so stride % 32 == 8 -> conflict-free fragment LDS.
// ---------------------------------------------------------------------------
#define BM 128
#define BN 128
#define BK 16
#define SSTRIDE (BM + 8)   // 136; 136 % 32 == 8

__device__ __forceinline__ uint32_t f32_to_tf32(float f) {
    uint32_t r;
    asm("cvt.rna.tf32.f32 %0, %1;" : "=r"(r) : "f"(f));
    return r;
}

__global__ __launch_bounds__(256, 2)
void tf32_gemm_kernel(const float* __restrict__ A,   // [M, 512]
                      const float* __restrict__ B,   // [512, 512]
                      float* __restrict__ C,         // [M, 512]
                      int M) {
    constexpr int N = 512, K = 512;

    __shared__ uint32_t As[BK][SSTRIDE];   // k-major (transposed) A tile
    __shared__ uint32_t Bs[BK][SSTRIDE];   // k-major B tile

    const int tid  = threadIdx.x;
    const int wid  = tid >> 5;
    const int lane = tid & 31;
    const int g    = lane >> 2;    // groupID      0..7
    const int tg   = lane & 3;     // tid-in-group 0..3

    const int wm = (wid >> 1) * 32;   // warp M offset within CTA tile
    const int wn = (wid & 1) * 64;    // warp N offset within CTA tile

    const int m_base = blockIdx.y * BM;
    const int n_base = blockIdx.x * BN;

    // A loader: 128 rows x 16 k = 512 float4; 2 per thread
    // B loader: 16 k-rows x 128 cols = 512 float4; 2 per thread
    float acc[2][8][4];
    #pragma unroll
    for (int mi = 0; mi < 2; mi++)
        #pragma unroll
        for (int ni = 0; ni < 8; ni++)
            #pragma unroll
            for (int r = 0; r < 4; r++) acc[mi][ni][r] = 0.0f;

    for (int k0 = 0; k0 < K; k0 += BK) {
        // ---- load A tile (guard M), convert to tf32, store transposed ----
        #pragma unroll
        for (int j = 0; j < 2; j++) {
            const int f   = tid * 2 + j;
            const int row = f >> 2;            // 0..127
            const int kq  = (f & 3) * 4;       // 0,4,8,12
            float4 v = make_float4(0.f, 0.f, 0.f, 0.f);
            if (m_base + row < M)
                v = *reinterpret_cast<const float4*>(
                        A + (size_t)(m_base + row) * K + k0 + kq);
            As[kq + 0][row] = f32_to_tf32(v.x);
            As[kq + 1][row] = f32_to_tf32(v.y);
            As[kq + 2][row] = f32_to_tf32(v.z);
            As[kq + 3][row] = f32_to_tf32(v.w);
        }
        // ---- load B tile, convert, store (no transpose) ----
        #pragma unroll
        for (int j = 0; j < 2; j++) {
            const int f    = tid * 2 + j;
            const int brow = f >> 5;           // 0..15
            const int bc4  = (f & 31) * 4;     // 0..124
            float4 v = *reinterpret_cast<const float4*>(
                           B + (size_t)(k0 + brow) * N + n_base + bc4);
            uint4 t;
            t.x = f32_to_tf32(v.x);
            t.y = f32_to_tf32(v.y);
            t.z = f32_to_tf32(v.z);
            t.w = f32_to_tf32(v.w);
            *reinterpret_cast<uint4*>(&Bs[brow][bc4]) = t;
        }
        __syncthreads();

        // ---- compute: 2 k-steps of 8 ----
        #pragma unroll
        for (int ks = 0; ks < BK; ks += 8) {
            uint32_t a[2][4], b[8][2];
            #pragma unroll
            for (int mi = 0; mi < 2; mi++) {
                const int m0 = wm + mi * 16;
                a[mi][0] = As[ks + tg    ][m0 + g    ];
                a[mi][1] = As[ks + tg    ][m0 + g + 8];
                a[mi][2] = As[ks + tg + 4][m0 + g    ];
                a[mi][3] = As[ks + tg + 4][m0 + g + 8];
            }
            #pragma unroll
            for (int ni = 0; ni < 8; ni++) {
                const int n0 = wn + ni * 8;
                b[ni][0] = Bs[ks + tg    ][n0 + g];
                b[ni][1] = Bs[ks + tg + 4][n0 + g];
            }
            #pragma unroll
            for (int mi = 0; mi < 2; mi++)
                #pragma unroll
                for (int ni = 0; ni < 8; ni++) {
                    asm volatile(
                        "mma.sync.aligned.m16n8k8.row.col.f32.tf32.tf32.f32 "
                        "{%0,%1,%2,%3}, {%4,%5,%6,%7}, {%8,%9}, {%0,%1,%2,%3};"
                        : "+f"(acc[mi][ni][0]), "+f"(acc[mi][ni][1]),
                          "+f"(acc[mi][ni][2]), "+f"(acc[mi][ni][3])
                        : "r"(a[mi][0]), "r"(a[mi][1]), "r"(a[mi][2]), "r"(a[mi][3]),
                          "r"(b[ni][0]), "r"(b[ni][1]));
                }
        }
        __syncthreads();
    }

    // ---- epilogue: c0,c1 = (row, 2tg..2tg+1), c2,c3 = (row+8, ...) ----
    #pragma unroll
    for (int mi = 0; mi < 2; mi++) {
        const int row0 = m_base + wm + mi * 16 + g;
        const int row1 = row0 + 8;
        #pragma unroll
        for (int ni = 0; ni < 8; ni++) {
            const int col = n_base + wn + ni * 8 + 2 * tg;
            if (row0 < M) {
                float2 v = make_float2(acc[mi][ni][0], acc[mi][ni][1]);
                *reinterpret_cast<float2*>(C + (size_t)row0 * N + col) = v;
            }
            if (row1 < M) {
                float2 v = make_float2(acc[mi][ni][2], acc[mi][ni][3]);
                *reinterpret_cast<float2*>(C + (size_t)row1 * N + col) = v;
            }
        }
    }
}

// ---------------------------------------------------------------------------
// Kernel 3: COO scatter. One warp per edge, red.global.add.v4.f32.
// ---------------------------------------------------------------------------
__global__ __launch_bounds__(256)
void scatter_kernel(const int* __restrict__ rows,
                    const int* __restrict__ cols,
                    const float* __restrict__ vals,
                    float* __restrict__ out,
                    int E) {
    const int warp = (blockIdx.x * blockDim.x + threadIdx.x) >> 5;
    const int lane = threadIdx.x & 31;
    if (warp >= E) return;

    const int r = rows[warp];
    const int c = cols[warp];
    const float v = vals[warp];

    const float4* s = reinterpret_cast<const float4*>(g_support + (size_t)c * D);
    float4* o = reinterpret_cast<float4*>(out + (size_t)r * D);

    #pragma unroll
    for (int w = 0; w < 4; w++) {
        const int idx = lane + w * 32;
        float4 m = s[idx];
        m.x *= v; m.y *= v; m.z *= v; m.w *= v;
        asm volatile(
            "red.global.add.v4.f32 [%0], {%1, %2, %3, %4};"
            :: "l"(o + idx), "f"(m.x), "f"(m.y), "f"(m.z), "f"(m.w)
            : "memory");
    }
}

// ---------------------------------------------------------------------------
// Launch
// ---------------------------------------------------------------------------
extern "C" void kernel_launch(void* const* d_in, const int* in_sizes, int n_in,
                              void* d_out, int out_size) {
    const float* x        = (const float*)d_in[0];
    const int*   adj_rows = (const int*)  d_in[1];
    const int*   adj_cols = (const int*)  d_in[2];
    const float* adj_vals = (const float*)d_in[3];
    const float* weight   = (const float*)d_in[4];
    const float* bias     = (const float*)d_in[5];
    float* out = (float*)d_out;

    const int M = in_sizes[0] / D;   // N_NODES
    const int E = in_sizes[1];       // N_EDGES

    // 1) out = broadcast(bias)
    {
        int total_f4 = (M * D) / 4;
        int threads = 256;
        int blocks = (total_f4 + threads - 1) / threads;
        init_out_kernel<<<blocks, threads>>>(out, bias, total_f4);
    }

    // 2) support = x @ W  (tf32 tensor cores)
    {
        float* support;
        cudaGetSymbolAddress((void**)&support, g_support);
        dim3 grid(D / BN, (M + BM - 1) / BM);
        tf32_gemm_kernel<<<grid, 256>>>(x, weight, support, M);
    }

    // 3) out += scatter-add over edges
    {
        int warps_per_block = 256 / 32;
        int blocks = (E + warps_per_block - 1) / warps_per_block;
        scatter_kernel<<<blocks, 256>>>(adj_rows, adj_cols, adj_vals, out, E);
    }
}

// round 3
// speedup vs baseline: 2.1818x; 1.2375x over previous
#include <cuda_runtime.h>
#include <cuda_bf16.h>
#include <cstdint>

// ---------------------------------------------------------------------------
// GraphConvolution: out = SpMM(COO adj, x @ W) + bias
// Round 2: counting-sort edges by destination row -> one warp per output row
// accumulates in registers and writes out = acc + bias with plain stores.
// Eliminates all global RED read-modify-write traffic on `out`.
// ---------------------------------------------------------------------------

#define D 512
#define MAX_NODES 50000
#define MAX_EDGES 400000

__device__ float g_support[(size_t)MAX_NODES * D];
__device__ int   g_counts[MAX_NODES];
__device__ int   g_offsets[MAX_NODES + 1];
__device__ int   g_cursors[MAX_NODES];
__device__ int2  g_perm[MAX_EDGES];      // (col, val-as-int) sorted by row

// ---------------------------------------------------------------------------
// Prep 1: zero histogram
// ---------------------------------------------------------------------------
__global__ void zero_counts_kernel(int n) {
    int i = blockIdx.x * blockDim.x + threadIdx.x;
    if (i < n) g_counts[i] = 0;
}

// ---------------------------------------------------------------------------
// Prep 2: histogram of destination rows
// ---------------------------------------------------------------------------
__global__ void hist_kernel(const int* __restrict__ rows, int E) {
    int e = blockIdx.x * blockDim.x + threadIdx.x;
    if (e < E) atomicAdd(&g_counts[rows[e]], 1);
}

// ---------------------------------------------------------------------------
// Prep 3: exclusive scan (single block, 1024 threads, iterative with carry)
// Writes g_offsets[0..n] and g_cursors[0..n-1].
// ---------------------------------------------------------------------------
__global__ __launch_bounds__(1024)
void scan_kernel(int n) {
    __shared__ int warp_sums[32];
    __shared__ int s_carry;
    const int tid  = threadIdx.x;
    const int lane = tid & 31;
    const int wid  = tid >> 5;

    if (tid == 0) s_carry = 0;
    __syncthreads();

    for (int base = 0; base < n; base += 1024) {
        const int i = base + tid;
        const int v = (i < n) ? g_counts[i] : 0;

        // warp-inclusive scan
        int x = v;
        #pragma unroll
        for (int d = 1; d < 32; d <<= 1) {
            int y = __shfl_up_sync(0xffffffffu, x, d);
            if (lane >= d) x += y;
        }
        if (lane == 31) warp_sums[wid] = x;
        __syncthreads();

        if (wid == 0) {
            int w = warp_sums[lane];
            #pragma unroll
            for (int d = 1; d < 32; d <<= 1) {
                int y = __shfl_up_sync(0xffffffffu, w, d);
                if (lane >= d) w += y;
            }
            warp_sums[lane] = w;   // inclusive over warp sums
        }
        __syncthreads();

        const int warp_prefix = (wid == 0) ? 0 : warp_sums[wid - 1];
        const int excl = s_carry + warp_prefix + x - v;
        if (i < n) {
            g_offsets[i] = excl;
            g_cursors[i] = excl;
        }
        const int block_total = warp_sums[31];
        __syncthreads();                 // everyone done reading s_carry
        if (tid == 0) s_carry += block_total;
        __syncthreads();
    }
    if (tid == 0) g_offsets[n] = s_carry;
}

// ---------------------------------------------------------------------------
// Prep 4: placement — scatter (col, val) into row-sorted order
// ---------------------------------------------------------------------------
__global__ void place_kernel(const int* __restrict__ rows,
                             const int* __restrict__ cols,
                             const float* __restrict__ vals,
                             int E) {
    int e = blockIdx.x * blockDim.x + threadIdx.x;
    if (e >= E) return;
    int pos = atomicAdd(&g_cursors[rows[e]], 1);
    g_perm[pos] = make_int2(cols[e], __float_as_int(vals[e]));
}

// ---------------------------------------------------------------------------
// TF32 tensor-core GEMM  C[M,512] = A[M,512] * B[512,512]  (unchanged from R1)
// ---------------------------------------------------------------------------
#define BM 128
#define BN 128
#define BK 16
#define SSTRIDE (BM + 8)

__device__ __forceinline__ uint32_t f32_to_tf32(float f) {
    uint32_t r;
    asm("cvt.rna.tf32.f32 %0, %1;" : "=r"(r) : "f"(f));
    return r;
}

__global__ __launch_bounds__(256, 2)
void tf32_gemm_kernel(const float* __restrict__ A,
                      const float* __restrict__ B,
                      float* __restrict__ C,
                      int M) {
    constexpr int N = 512, K = 512;

    __shared__ uint32_t As[BK][SSTRIDE];
    __shared__ uint32_t Bs[BK][SSTRIDE];

    const int tid  = threadIdx.x;
    const int wid  = tid >> 5;
    const int lane = tid & 31;
    const int g    = lane >> 2;
    const int tg   = lane & 3;

    const int wm = (wid >> 1) * 32;
    const int wn = (wid & 1) * 64;

    const int m_base = blockIdx.y * BM;
    const int n_base = blockIdx.x * BN;

    float acc[2][8][4];
    #pragma unroll
    for (int mi = 0; mi < 2; mi++)
        #pragma unroll
        for (int ni = 0; ni < 8; ni++)
            #pragma unroll
            for (int r = 0; r < 4; r++) acc[mi][ni][r] = 0.0f;

    for (int k0 = 0; k0 < K; k0 += BK) {
        #pragma unroll
        for (int j = 0; j < 2; j++) {
            const int f   = tid * 2 + j;
            const int row = f >> 2;
            const int kq  = (f & 3) * 4;
            float4 v = make_float4(0.f, 0.f, 0.f, 0.f);
            if (m_base + row < M)
                v = *reinterpret_cast<const float4*>(
                        A + (size_t)(m_base + row) * K + k0 + kq);
            As[kq + 0][row] = f32_to_tf32(v.x);
            As[kq + 1][row] = f32_to_tf32(v.y);
            As[kq + 2][row] = f32_to_tf32(v.z);
            As[kq + 3][row] = f32_to_tf32(v.w);
        }
        #pragma unroll
        for (int j = 0; j < 2; j++) {
            const int f    = tid * 2 + j;
            const int brow = f >> 5;
            const int bc4  = (f & 31) * 4;
            float4 v = *reinterpret_cast<const float4*>(
                           B + (size_t)(k0 + brow) * N + n_base + bc4);
            uint4 t;
            t.x = f32_to_tf32(v.x);
            t.y = f32_to_tf32(v.y);
            t.z = f32_to_tf32(v.z);
            t.w = f32_to_tf32(v.w);
            *reinterpret_cast<uint4*>(&Bs[brow][bc4]) = t;
        }
        __syncthreads();

        #pragma unroll
        for (int ks = 0; ks < BK; ks += 8) {
            uint32_t a[2][4], b[8][2];
            #pragma unroll
            for (int mi = 0; mi < 2; mi++) {
                const int m0 = wm + mi * 16;
                a[mi][0] = As[ks + tg    ][m0 + g    ];
                a[mi][1] = As[ks + tg    ][m0 + g + 8];
                a[mi][2] = As[ks + tg + 4][m0 + g    ];
                a[mi][3] = As[ks + tg + 4][m0 + g + 8];
            }
            #pragma unroll
            for (int ni = 0; ni < 8; ni++) {
                const int n0 = wn + ni * 8;
                b[ni][0] = Bs[ks + tg    ][n0 + g];
                b[ni][1] = Bs[ks + tg + 4][n0 + g];
            }
            #pragma unroll
            for (int mi = 0; mi < 2; mi++)
                #pragma unroll
                for (int ni = 0; ni < 8; ni++) {
                    asm volatile(
                        "mma.sync.aligned.m16n8k8.row.col.f32.tf32.tf32.f32 "
                        "{%0,%1,%2,%3}, {%4,%5,%6,%7}, {%8,%9}, {%0,%1,%2,%3};"
                        : "+f"(acc[mi][ni][0]), "+f"(acc[mi][ni][1]),
                          "+f"(acc[mi][ni][2]), "+f"(acc[mi][ni][3])
                        : "r"(a[mi][0]), "r"(a[mi][1]), "r"(a[mi][2]), "r"(a[mi][3]),
                          "r"(b[ni][0]), "r"(b[ni][1]));
                }
        }
        __syncthreads();
    }

    #pragma unroll
    for (int mi = 0; mi < 2; mi++) {
        const int row0 = m_base + wm + mi * 16 + g;
        const int row1 = row0 + 8;
        #pragma unroll
        for (int ni = 0; ni < 8; ni++) {
            const int col = n_base + wn + ni * 8 + 2 * tg;
            if (row0 < M) {
                float2 v = make_float2(acc[mi][ni][0], acc[mi][ni][1]);
                *reinterpret_cast<float2*>(C + (size_t)row0 * N + col) = v;
            }
            if (row1 < M) {
                float2 v = make_float2(acc[mi][ni][2], acc[mi][ni][3]);
                *reinterpret_cast<float2*>(C + (size_t)row1 * N + col) = v;
            }
        }
    }
}

// ---------------------------------------------------------------------------
// Row-gather: one warp per output row. Accumulate all edges in registers,
// write out = acc + bias with plain STG.128 (no atomics, covers 0-edge rows).
// ---------------------------------------------------------------------------
__global__ __launch_bounds__(256)
void row_gather_kernel(const float* __restrict__ bias,
                       float* __restrict__ out,
                       int n_rows) {
    const int warp = (blockIdx.x * blockDim.x + threadIdx.x) >> 5;
    const int lane = threadIdx.x & 31;
    if (warp >= n_rows) return;

    const int s = g_offsets[warp];
    const int e = g_offsets[warp + 1];

    float4 acc[4];
    #pragma unroll
    for (int w = 0; w < 4; w++) acc[w] = make_float4(0.f, 0.f, 0.f, 0.f);

    int i = s;
    // 2-edge unrolled main loop for memory-level parallelism
    for (; i + 1 < e; i += 2) {
        const int2 cv0 = g_perm[i];
        const int2 cv1 = g_perm[i + 1];
        const float v0 = __int_as_float(cv0.y);
        const float v1 = __int_as_float(cv1.y);
        const float4* s0 = reinterpret_cast<const float4*>(
                               g_support + (size_t)cv0.x * D);
        const float4* s1 = reinterpret_cast<const float4*>(
                               g_support + (size_t)cv1.x * D);
        #pragma unroll
        for (int w = 0; w < 4; w++) {
            const float4 m0 = s0[lane + w * 32];
            const float4 m1 = s1[lane + w * 32];
            acc[w].x += v0 * m0.x + v1 * m1.x;
            acc[w].y += v0 * m0.y + v1 * m1.y;
            acc[w].z += v0 * m0.z + v1 * m1.z;
            acc[w].w += v0 * m0.w + v1 * m1.w;
        }
    }
    for (; i < e; i++) {
        const int2 cv = g_perm[i];
        const float v = __int_as_float(cv.y);
        const float4* sp = reinterpret_cast<const float4*>(
                               g_support + (size_t)cv.x * D);
        #pragma unroll
        for (int w = 0; w < 4; w++) {
            const float4 m = sp[lane + w * 32];
            acc[w].x += v * m.x;
            acc[w].y += v * m.y;
            acc[w].z += v * m.z;
            acc[w].w += v * m.w;
        }
    }

    const float4* bp = reinterpret_cast<const float4*>(bias);
    float4* op = reinterpret_cast<float4*>(out + (size_t)warp * D);
    #pragma unroll
    for (int w = 0; w < 4; w++) {
        const float4 b = bp[lane + w * 32];
        float4 r;
        r.x = acc[w].x + b.x;
        r.y = acc[w].y + b.y;
        r.z = acc[w].z + b.z;
        r.w = acc[w].w + b.w;
        op[lane + w * 32] = r;
    }
}

// ---------------------------------------------------------------------------
// Launch
// ---------------------------------------------------------------------------
extern "C" void kernel_launch(void* const* d_in, const int* in_sizes, int n_in,
                              void* d_out, int out_size) {
    const float* x        = (const float*)d_in[0];
    const int*   adj_rows = (const int*)  d_in[1];
    const int*   adj_cols = (const int*)  d_in[2];
    const float* adj_vals = (const float*)d_in[3];
    const float* weight   = (const float*)d_in[4];
    const float* bias     = (const float*)d_in[5];
    float* out = (float*)d_out;

    const int M = in_sizes[0] / D;   // N_NODES
    const int E = in_sizes[1];       // N_EDGES

    // --- CSR prep (counting sort by destination row) ---
    zero_counts_kernel<<<(M + 255) / 256, 256>>>(M);
    hist_kernel<<<(E + 255) / 256, 256>>>(adj_rows, E);
    scan_kernel<<<1, 1024>>>(M);
    place_kernel<<<(E + 255) / 256, 256>>>(adj_rows, adj_cols, adj_vals, E);

    // --- support = x @ W (tf32 tensor cores) ---
    {
        float* support;
        cudaGetSymbolAddress((void**)&support, g_support);
        dim3 grid(D / BN, (M + BM - 1) / BM);
        tf32_gemm_kernel<<<grid, 256>>>(x, weight, support, M);
    }

    // --- out[r] = sum_{edges->r} val * support[col] + bias ---
    {
        int warps_per_block = 256 / 32;
        int blocks = (M + warps_per_block - 1) / warps_per_block;
        row_gather_kernel<<<blocks, 256>>>(bias, out, M);
    }
}